// round 2
// baseline (speedup 1.0000x reference)
#include <cuda_runtime.h>
#include <cstdint>

#define N_NODES 50000
#define N_EDGES 800000
#define IN_DIM  128
#define OUT_DIM 128
#define EDGE_DIM 64

typedef unsigned long long u64;

// Scratch for node projections (allocation-free per harness rules).
__device__ __align__(16) float g_HU[(size_t)N_NODES * OUT_DIM];
__device__ __align__(16) float g_HW[(size_t)N_NODES * OUT_DIM];
__device__ int g_idx_is64;

__device__ __forceinline__ u64 pack2(float lo, float hi) {
    u64 r;
    asm("mov.b64 %0, {%1, %2};" : "=l"(r) : "f"(lo), "f"(hi));
    return r;
}
__device__ __forceinline__ void fma2(u64& d, u64 a, u64 b) {
    asm("fma.rn.f32x2 %0, %1, %2, %3;" : "=l"(d) : "l"(a), "l"(b), "l"(d));
}
__device__ __forceinline__ float2 unpack2(u64 v) {
    float2 f;
    asm("mov.b64 {%0, %1}, %2;" : "=f"(f.x), "=f"(f.y) : "l"(v));
    return f;
}

// ---------------------------------------------------------------------------
// Index-dtype detection: if edge_index is int64 (LE) with values < 50000,
// every odd 32-bit word of the first 256 pairs is 0. Deterministic each call.
// ---------------------------------------------------------------------------
__global__ void detect_idx_kernel(const int* __restrict__ ei32) {
    if (threadIdx.x == 0 && blockIdx.x == 0) {
        int all_zero = 1;
        for (int i = 0; i < 256; ++i) {
            if (ei32[2 * i + 1] != 0) { all_zero = 0; break; }
        }
        g_idx_is64 = all_zero;
    }
}

__device__ __forceinline__ int fetch_idx(const int* __restrict__ ei32,
                                         int is64, size_t pos) {
    int v = is64 ? ei32[2 * pos] : ei32[pos];
    // clamp: wrong-dtype guess becomes a rel_err signal, not a crash
    v = v < 0 ? 0 : (v >= N_NODES ? N_NODES - 1 : v);
    return v;
}

// ---------------------------------------------------------------------------
// Node projection: dst[n][o] = sum_k h[n][k] * W[o][k]
// Block tile: 128 nodes x 128 outs, K staged by 32. Thread: 8 nodes x 8 outs.
// ---------------------------------------------------------------------------
__global__ __launch_bounds__(256, 2)
void node_proj_kernel(const float* __restrict__ h,
                      const float* __restrict__ W,
                      int which)   // 0 -> g_HU, 1 -> g_HW
{
    __shared__ __align__(16) float Wsh[32][128];  // [k][o]
    __shared__ __align__(16) float Hsh[32][128];  // [k][node]

    float* __restrict__ dst = which ? g_HW : g_HU;

    const int tid = threadIdx.x;
    const int tx  = tid & 15;   // outs: tx*8 .. tx*8+7
    const int ty  = tid >> 4;   // nodes: ty*8 .. ty*8+7
    const int n0  = blockIdx.x * 128;

    u64 acc[4][8];
#pragma unroll
    for (int i = 0; i < 4; ++i)
#pragma unroll
        for (int j = 0; j < 8; ++j) acc[i][j] = 0ULL;

#pragma unroll 1
    for (int s = 0; s < 4; ++s) {
        __syncthreads();
#pragma unroll
        for (int it = 0; it < 4; ++it) {
            int idx = it * 256 + tid;      // 0..1023 float4s
            int o   = idx >> 3;            // 0..127
            int kq  = idx & 7;             // 0..7
            float4 w = *reinterpret_cast<const float4*>(W + (size_t)o * IN_DIM + s * 32 + kq * 4);
            Wsh[kq * 4 + 0][o] = w.x;
            Wsh[kq * 4 + 1][o] = w.y;
            Wsh[kq * 4 + 2][o] = w.z;
            Wsh[kq * 4 + 3][o] = w.w;
        }
#pragma unroll
        for (int it = 0; it < 4; ++it) {
            int idx = it * 256 + tid;      // 0..1023 float4s
            int ln  = idx >> 3;            // 0..127
            int kq  = idx & 7;
            int n   = n0 + ln;
            float4 v = make_float4(0.f, 0.f, 0.f, 0.f);
            if (n < N_NODES)
                v = *reinterpret_cast<const float4*>(h + (size_t)n * IN_DIM + s * 32 + kq * 4);
            Hsh[kq * 4 + 0][ln] = v.x;
            Hsh[kq * 4 + 1][ln] = v.y;
            Hsh[kq * 4 + 2][ln] = v.z;
            Hsh[kq * 4 + 3][ln] = v.w;
        }
        __syncthreads();

#pragma unroll
        for (int k = 0; k < 32; ++k) {
            float4 wa = *reinterpret_cast<const float4*>(&Wsh[k][tx * 8]);
            float4 wb = *reinterpret_cast<const float4*>(&Wsh[k][tx * 8 + 4]);
            u64 w2[8];
            w2[0] = pack2(wa.x, wa.x); w2[1] = pack2(wa.y, wa.y);
            w2[2] = pack2(wa.z, wa.z); w2[3] = pack2(wa.w, wa.w);
            w2[4] = pack2(wb.x, wb.x); w2[5] = pack2(wb.y, wb.y);
            w2[6] = pack2(wb.z, wb.z); w2[7] = pack2(wb.w, wb.w);
            u64 ev[4];
#pragma unroll
            for (int i = 0; i < 4; ++i)
                ev[i] = *reinterpret_cast<const u64*>(&Hsh[k][ty * 8 + 2 * i]);
#pragma unroll
            for (int i = 0; i < 4; ++i)
#pragma unroll
                for (int j = 0; j < 8; ++j)
                    fma2(acc[i][j], ev[i], w2[j]);
        }
    }

#pragma unroll
    for (int i = 0; i < 4; ++i) {
        int na = n0 + ty * 8 + 2 * i;
        float2 v0 = unpack2(acc[i][0]), v1 = unpack2(acc[i][1]);
        float2 v2 = unpack2(acc[i][2]), v3 = unpack2(acc[i][3]);
        float2 v4 = unpack2(acc[i][4]), v5 = unpack2(acc[i][5]);
        float2 v6 = unpack2(acc[i][6]), v7 = unpack2(acc[i][7]);
        if (na < N_NODES) {
            float* p = dst + (size_t)na * OUT_DIM + tx * 8;
            *reinterpret_cast<float4*>(p)     = make_float4(v0.x, v1.x, v2.x, v3.x);
            *reinterpret_cast<float4*>(p + 4) = make_float4(v4.x, v5.x, v6.x, v7.x);
        }
        if (na + 1 < N_NODES) {
            float* p = dst + (size_t)(na + 1) * OUT_DIM + tx * 8;
            *reinterpret_cast<float4*>(p)     = make_float4(v0.y, v1.y, v2.y, v3.y);
            *reinterpret_cast<float4*>(p + 4) = make_float4(v4.y, v5.y, v6.y, v7.y);
        }
    }
}

// ---------------------------------------------------------------------------
// Fused edge kernel: out[eid][o] = sum_k e[eid][k]*We[o][k] + hu[src][o] + hw[tgt][o]
// Block tile: 128 edges x 128 outs, K=64. Thread: 8 edges x 8 outs.
// ---------------------------------------------------------------------------
__global__ __launch_bounds__(256, 2)
void edge_kernel(const float* __restrict__ e,
                 const int* __restrict__ ei32,
                 const float* __restrict__ We,
                 float* __restrict__ out)
{
    __shared__ __align__(16) float Wsh[EDGE_DIM][128];  // [k][o]   32 KB
    __shared__ __align__(16) float Esh[16][128];        // [k][edge] 8 KB

    const int tid  = threadIdx.x;
    const int tx   = tid & 15;   // outs: tx*8 .. tx*8+7
    const int ty   = tid >> 4;   // edges: ty*8 .. ty*8+7
    const int e0   = blockIdx.x * 128;
    const int is64 = g_idx_is64;

    // Load full We: We[o][kq*4..] -> Wsh[kq*4+j][o]
#pragma unroll
    for (int it = 0; it < 8; ++it) {
        int idx = it * 256 + tid;       // 0..2047 float4s
        int o   = idx >> 4;             // 0..127
        int kq  = idx & 15;             // 0..15
        float4 w = reinterpret_cast<const float4*>(We)[idx];
        Wsh[kq * 4 + 0][o] = w.x;
        Wsh[kq * 4 + 1][o] = w.y;
        Wsh[kq * 4 + 2][o] = w.z;
        Wsh[kq * 4 + 3][o] = w.w;
    }

    u64 acc[4][8];
#pragma unroll
    for (int i = 0; i < 4; ++i)
#pragma unroll
        for (int j = 0; j < 8; ++j) acc[i][j] = 0ULL;

#pragma unroll 1
    for (int s = 0; s < 4; ++s) {
        __syncthreads();
#pragma unroll
        for (int it = 0; it < 2; ++it) {
            int idx = it * 256 + tid;   // 0..511 float4s
            int le  = idx >> 2;         // 0..127
            int kq  = idx & 3;          // 0..3
            float4 v = *reinterpret_cast<const float4*>(
                e + (size_t)(e0 + le) * EDGE_DIM + s * 16 + kq * 4);
            Esh[kq * 4 + 0][le] = v.x;
            Esh[kq * 4 + 1][le] = v.y;
            Esh[kq * 4 + 2][le] = v.z;
            Esh[kq * 4 + 3][le] = v.w;
        }
        __syncthreads();

#pragma unroll
        for (int k = 0; k < 16; ++k) {
            int kk = s * 16 + k;
            float4 wa = *reinterpret_cast<const float4*>(&Wsh[kk][tx * 8]);
            float4 wb = *reinterpret_cast<const float4*>(&Wsh[kk][tx * 8 + 4]);
            u64 w2[8];
            w2[0] = pack2(wa.x, wa.x); w2[1] = pack2(wa.y, wa.y);
            w2[2] = pack2(wa.z, wa.z); w2[3] = pack2(wa.w, wa.w);
            w2[4] = pack2(wb.x, wb.x); w2[5] = pack2(wb.y, wb.y);
            w2[6] = pack2(wb.z, wb.z); w2[7] = pack2(wb.w, wb.w);
            u64 ev[4];
#pragma unroll
            for (int i = 0; i < 4; ++i)
                ev[i] = *reinterpret_cast<const u64*>(&Esh[k][ty * 8 + 2 * i]);
#pragma unroll
            for (int i = 0; i < 4; ++i)
#pragma unroll
                for (int j = 0; j < 8; ++j)
                    fma2(acc[i][j], ev[i], w2[j]);
        }
    }

    // Epilogue: gather hu[src], hw[tgt] (L2-resident) and store coalesced float4s.
#pragma unroll
    for (int i = 0; i < 4; ++i) {
        int ea = e0 + ty * 8 + 2 * i;   // edge pair (ea, ea+1)
        int sa = fetch_idx(ei32, is64, (size_t)ea);
        int ta = fetch_idx(ei32, is64, (size_t)N_EDGES + ea);
        int sb = fetch_idx(ei32, is64, (size_t)ea + 1);
        int tb = fetch_idx(ei32, is64, (size_t)N_EDGES + ea + 1);

        float2 v0 = unpack2(acc[i][0]), v1 = unpack2(acc[i][1]);
        float2 v2 = unpack2(acc[i][2]), v3 = unpack2(acc[i][3]);
        float2 v4 = unpack2(acc[i][4]), v5 = unpack2(acc[i][5]);
        float2 v6 = unpack2(acc[i][6]), v7 = unpack2(acc[i][7]);

        const float* hua = g_HU + (size_t)sa * OUT_DIM + tx * 8;
        const float* hwa = g_HW + (size_t)ta * OUT_DIM + tx * 8;
        float4 A0 = *reinterpret_cast<const float4*>(hua);
        float4 A1 = *reinterpret_cast<const float4*>(hua + 4);
        float4 B0 = *reinterpret_cast<const float4*>(hwa);
        float4 B1 = *reinterpret_cast<const float4*>(hwa + 4);
        float* pa = out + (size_t)ea * OUT_DIM + tx * 8;
        *reinterpret_cast<float4*>(pa) =
            make_float4(v0.x + A0.x + B0.x, v1.x + A0.y + B0.y,
                        v2.x + A0.z + B0.z, v3.x + A0.w + B0.w);
        *reinterpret_cast<float4*>(pa + 4) =
            make_float4(v4.x + A1.x + B1.x, v5.x + A1.y + B1.y,
                        v6.x + A1.z + B1.z, v7.x + A1.w + B1.w);

        const float* hub = g_HU + (size_t)sb * OUT_DIM + tx * 8;
        const float* hwb = g_HW + (size_t)tb * OUT_DIM + tx * 8;
        float4 C0 = *reinterpret_cast<const float4*>(hub);
        float4 C1 = *reinterpret_cast<const float4*>(hub + 4);
        float4 D0 = *reinterpret_cast<const float4*>(hwb);
        float4 D1 = *reinterpret_cast<const float4*>(hwb + 4);
        float* pb = out + (size_t)(ea + 1) * OUT_DIM + tx * 8;
        *reinterpret_cast<float4*>(pb) =
            make_float4(v0.y + C0.x + D0.x, v1.y + C0.y + D0.y,
                        v2.y + C0.z + D0.z, v3.y + C0.w + D0.w);
        *reinterpret_cast<float4*>(pb + 4) =
            make_float4(v4.y + C1.x + D1.x, v5.y + C1.y + D1.y,
                        v6.y + C1.z + D1.z, v7.y + C1.w + D1.w);
    }
}

extern "C" void kernel_launch(void* const* d_in, const int* in_sizes, int n_in,
                              void* d_out, int out_size)
{
    const float* h   = (const float*)d_in[0];       // [50000,128]
    const float* e   = (const float*)d_in[1];       // [800000,64]
    const int*   ei  = (const int*)d_in[2];         // [2,800000] int32 (or int64, detected)
    const float* We  = (const float*)d_in[3];       // [128,64]
    const float* Whu = (const float*)d_in[4];       // [128,128]
    const float* Whw = (const float*)d_in[5];       // [128,128]
    float*       out = (float*)d_out;               // [800000,128]

    detect_idx_kernel<<<1, 32>>>(ei);
    const int node_blocks = (N_NODES + 127) / 128;  // 391
    node_proj_kernel<<<node_blocks, 256>>>(h, Whu, 0);
    node_proj_kernel<<<node_blocks, 256>>>(h, Whw, 1);
    edge_kernel<<<N_EDGES / 128, 256>>>(e, ei, We, out);
}

// round 3
// speedup vs baseline: 1.2844x; 1.2844x over previous
#include <cuda_runtime.h>
#include <cstdint>

#define N_NODES 50000
#define N_EDGES 800000
#define IN_DIM  128
#define OUT_DIM 128
#define EDGE_DIM 64

typedef unsigned long long u64;

// Scratch for node projections (allocation-free per harness rules).
__device__ __align__(16) float g_HU[(size_t)N_NODES * OUT_DIM];
__device__ __align__(16) float g_HW[(size_t)N_NODES * OUT_DIM];
__device__ int g_idx_is64;

__device__ __forceinline__ u64 pack2(float lo, float hi) {
    u64 r;
    asm("mov.b64 %0, {%1, %2};" : "=l"(r) : "f"(lo), "f"(hi));
    return r;
}
__device__ __forceinline__ void fma2(u64& d, u64 a, u64 b) {
    asm("fma.rn.f32x2 %0, %1, %2, %3;" : "=l"(d) : "l"(a), "l"(b), "l"(d));
}
__device__ __forceinline__ float2 unpack2(u64 v) {
    float2 f;
    asm("mov.b64 {%0, %1}, %2;" : "=f"(f.x), "=f"(f.y) : "l"(v));
    return f;
}

// ---------------------------------------------------------------------------
// Index-dtype detection: if edge_index is int64 (LE) with values < 50000,
// every odd 32-bit word of the first 256 pairs is 0. Deterministic each call.
// ---------------------------------------------------------------------------
__global__ void detect_idx_kernel(const int* __restrict__ ei32) {
    if (threadIdx.x == 0 && blockIdx.x == 0) {
        int all_zero = 1;
        for (int i = 0; i < 256; ++i) {
            if (ei32[2 * i + 1] != 0) { all_zero = 0; break; }
        }
        g_idx_is64 = all_zero;
    }
}

__device__ __forceinline__ int fetch_idx(const int* __restrict__ ei32,
                                         int is64, size_t pos) {
    int v = is64 ? ei32[2 * pos] : ei32[pos];
    v = v < 0 ? 0 : (v >= N_NODES ? N_NODES - 1 : v);
    return v;
}

// ---------------------------------------------------------------------------
// Node projection (both W_hu and W_hw via blockIdx.y):
// dst[n][o] = sum_k h[n][k] * W[o][k]
// Block tile 128 nodes x 128 outs; thread tile 16 nodes x 4 outs.
// tx = lane (out-quad), ty = warp (16-node group). W LDS contiguous,
// H LDS full-warp broadcast. Rows padded to 132 floats (16B aligned).
// ---------------------------------------------------------------------------
__global__ __launch_bounds__(256, 2)
void node_proj_kernel(const float* __restrict__ h,
                      const float* __restrict__ Whu,
                      const float* __restrict__ Whw)
{
    __shared__ __align__(16) float Wsh[32][132];
    __shared__ __align__(16) float Hsh[32][132];

    const float* __restrict__ W   = blockIdx.y ? Whw : Whu;
    float*       __restrict__ dst = blockIdx.y ? g_HW : g_HU;

    const int tid = threadIdx.x;
    const int tx  = tid & 31;   // outs tx*4 .. tx*4+3
    const int ty  = tid >> 5;   // nodes ty*16 .. ty*16+15
    const int n0  = blockIdx.x * 128;

    u64 acc[8][4];
#pragma unroll
    for (int p = 0; p < 8; ++p)
#pragma unroll
        for (int j = 0; j < 4; ++j) acc[p][j] = 0ULL;

#pragma unroll 1
    for (int s = 0; s < 4; ++s) {
        __syncthreads();
        // W stage: W[o][s*32 + kq*4 ..] -> Wsh[kq*4+j][o]
#pragma unroll
        for (int it = 0; it < 4; ++it) {
            int idx = it * 256 + tid;      // 0..1023 float4s
            int o   = idx >> 3;            // 0..127
            int kq  = idx & 7;             // 0..7
            float4 w = *reinterpret_cast<const float4*>(W + (size_t)o * IN_DIM + s * 32 + kq * 4);
            Wsh[kq * 4 + 0][o] = w.x;
            Wsh[kq * 4 + 1][o] = w.y;
            Wsh[kq * 4 + 2][o] = w.z;
            Wsh[kq * 4 + 3][o] = w.w;
        }
        // H stage (transposed): h[n][k] -> Hsh[k][n]
#pragma unroll
        for (int it = 0; it < 4; ++it) {
            int idx = it * 256 + tid;
            int ln  = idx >> 3;            // 0..127
            int kq  = idx & 7;
            int n   = n0 + ln;
            float4 v = make_float4(0.f, 0.f, 0.f, 0.f);
            if (n < N_NODES)
                v = *reinterpret_cast<const float4*>(h + (size_t)n * IN_DIM + s * 32 + kq * 4);
            Hsh[kq * 4 + 0][ln] = v.x;
            Hsh[kq * 4 + 1][ln] = v.y;
            Hsh[kq * 4 + 2][ln] = v.z;
            Hsh[kq * 4 + 3][ln] = v.w;
        }
        __syncthreads();

#pragma unroll
        for (int k = 0; k < 32; ++k) {
            float4 w = *reinterpret_cast<const float4*>(&Wsh[k][tx * 4]);
            u64 w2[4];
            w2[0] = pack2(w.x, w.x); w2[1] = pack2(w.y, w.y);
            w2[2] = pack2(w.z, w.z); w2[3] = pack2(w.w, w.w);
            u64 ev[8];
#pragma unroll
            for (int q = 0; q < 4; ++q) {
                ulonglong2 ep = *reinterpret_cast<const ulonglong2*>(&Hsh[k][ty * 16 + q * 4]);
                ev[2 * q]     = ep.x;
                ev[2 * q + 1] = ep.y;
            }
#pragma unroll
            for (int p = 0; p < 8; ++p)
#pragma unroll
                for (int j = 0; j < 4; ++j)
                    fma2(acc[p][j], ev[p], w2[j]);
        }
    }

#pragma unroll
    for (int p = 0; p < 8; ++p) {
        int na = n0 + ty * 16 + 2 * p;
        float2 v0 = unpack2(acc[p][0]), v1 = unpack2(acc[p][1]);
        float2 v2 = unpack2(acc[p][2]), v3 = unpack2(acc[p][3]);
        if (na < N_NODES)
            *reinterpret_cast<float4*>(dst + (size_t)na * OUT_DIM + tx * 4) =
                make_float4(v0.x, v1.x, v2.x, v3.x);
        if (na + 1 < N_NODES)
            *reinterpret_cast<float4*>(dst + (size_t)(na + 1) * OUT_DIM + tx * 4) =
                make_float4(v0.y, v1.y, v2.y, v3.y);
    }
}

// ---------------------------------------------------------------------------
// Fused edge kernel: out[eid][o] = sum_k e[eid][k]*We[o][k] + hu[src][o] + hw[tgt][o]
// Block tile 128 edges x 128 outs, K=64 (We resident, E staged by 16 with
// register prefetch). Thread tile 16 edges x 4 outs.
// ---------------------------------------------------------------------------
__global__ __launch_bounds__(256, 2)
void edge_kernel(const float* __restrict__ e,
                 const int* __restrict__ ei32,
                 const float* __restrict__ We,
                 float* __restrict__ out)
{
    __shared__ __align__(16) float Wsh[EDGE_DIM][132];  // [k][o]   33 KB
    __shared__ __align__(16) float Esh[16][132];        // [k][edge] 8.3 KB

    const int tid  = threadIdx.x;
    const int tx   = tid & 31;   // outs tx*4 .. tx*4+3
    const int ty   = tid >> 5;   // edges ty*16 .. ty*16+15
    const int e0   = blockIdx.x * 128;
    const int is64 = g_idx_is64;

    // One-time We fill: We[o][kq*4..] -> Wsh[kq*4+j][o]
#pragma unroll
    for (int it = 0; it < 8; ++it) {
        int idx = it * 256 + tid;       // 0..2047 float4s
        int o   = idx >> 4;             // 0..127
        int kq  = idx & 15;             // 0..15
        float4 w = reinterpret_cast<const float4*>(We)[idx];
        Wsh[kq * 4 + 0][o] = w.x;
        Wsh[kq * 4 + 1][o] = w.y;
        Wsh[kq * 4 + 2][o] = w.z;
        Wsh[kq * 4 + 3][o] = w.w;
    }

    u64 acc[8][4];
#pragma unroll
    for (int p = 0; p < 8; ++p)
#pragma unroll
        for (int j = 0; j < 4; ++j) acc[p][j] = 0ULL;

    // E stage fill: thread covers float4 idx {tid, 256+tid}
    const int le0 = tid >> 2,        kq0 = tid & 3;
    const int le1 = (256 + tid) >> 2, kq1 = (256 + tid) & 3;

    float4 pf0, pf1;
    // prefetch + store stage 0
    pf0 = *reinterpret_cast<const float4*>(e + (size_t)(e0 + le0) * EDGE_DIM + kq0 * 4);
    pf1 = *reinterpret_cast<const float4*>(e + (size_t)(e0 + le1) * EDGE_DIM + kq1 * 4);
    Esh[kq0 * 4 + 0][le0] = pf0.x; Esh[kq0 * 4 + 1][le0] = pf0.y;
    Esh[kq0 * 4 + 2][le0] = pf0.z; Esh[kq0 * 4 + 3][le0] = pf0.w;
    Esh[kq1 * 4 + 0][le1] = pf1.x; Esh[kq1 * 4 + 1][le1] = pf1.y;
    Esh[kq1 * 4 + 2][le1] = pf1.z; Esh[kq1 * 4 + 3][le1] = pf1.w;
    __syncthreads();

#pragma unroll 1
    for (int s = 0; s < 4; ++s) {
        if (s < 3) {  // prefetch next stage into registers
            pf0 = *reinterpret_cast<const float4*>(
                e + (size_t)(e0 + le0) * EDGE_DIM + (s + 1) * 16 + kq0 * 4);
            pf1 = *reinterpret_cast<const float4*>(
                e + (size_t)(e0 + le1) * EDGE_DIM + (s + 1) * 16 + kq1 * 4);
        }

#pragma unroll
        for (int k = 0; k < 16; ++k) {
            int kk = s * 16 + k;
            float4 w = *reinterpret_cast<const float4*>(&Wsh[kk][tx * 4]);
            u64 w2[4];
            w2[0] = pack2(w.x, w.x); w2[1] = pack2(w.y, w.y);
            w2[2] = pack2(w.z, w.z); w2[3] = pack2(w.w, w.w);
            u64 ev[8];
#pragma unroll
            for (int q = 0; q < 4; ++q) {
                ulonglong2 ep = *reinterpret_cast<const ulonglong2*>(&Esh[k][ty * 16 + q * 4]);
                ev[2 * q]     = ep.x;
                ev[2 * q + 1] = ep.y;
            }
#pragma unroll
            for (int p = 0; p < 8; ++p)
#pragma unroll
                for (int j = 0; j < 4; ++j)
                    fma2(acc[p][j], ev[p], w2[j]);
        }

        if (s < 3) {
            __syncthreads();
            Esh[kq0 * 4 + 0][le0] = pf0.x; Esh[kq0 * 4 + 1][le0] = pf0.y;
            Esh[kq0 * 4 + 2][le0] = pf0.z; Esh[kq0 * 4 + 3][le0] = pf0.w;
            Esh[kq1 * 4 + 0][le1] = pf1.x; Esh[kq1 * 4 + 1][le1] = pf1.y;
            Esh[kq1 * 4 + 2][le1] = pf1.z; Esh[kq1 * 4 + 3][le1] = pf1.w;
            __syncthreads();
        }
    }

    // Epilogue: gather hu[src], hw[tgt] (L2-resident), coalesced float4 stores.
#pragma unroll
    for (int p = 0; p < 8; ++p) {
        int ea = e0 + ty * 16 + 2 * p;   // edge pair (ea, ea+1)
        int sa = fetch_idx(ei32, is64, (size_t)ea);
        int ta = fetch_idx(ei32, is64, (size_t)N_EDGES + ea);
        int sb = fetch_idx(ei32, is64, (size_t)ea + 1);
        int tb = fetch_idx(ei32, is64, (size_t)N_EDGES + ea + 1);

        float2 v0 = unpack2(acc[p][0]), v1 = unpack2(acc[p][1]);
        float2 v2 = unpack2(acc[p][2]), v3 = unpack2(acc[p][3]);

        float4 A = *reinterpret_cast<const float4*>(g_HU + (size_t)sa * OUT_DIM + tx * 4);
        float4 B = *reinterpret_cast<const float4*>(g_HW + (size_t)ta * OUT_DIM + tx * 4);
        *reinterpret_cast<float4*>(out + (size_t)ea * OUT_DIM + tx * 4) =
            make_float4(v0.x + A.x + B.x, v1.x + A.y + B.y,
                        v2.x + A.z + B.z, v3.x + A.w + B.w);

        float4 C = *reinterpret_cast<const float4*>(g_HU + (size_t)sb * OUT_DIM + tx * 4);
        float4 D = *reinterpret_cast<const float4*>(g_HW + (size_t)tb * OUT_DIM + tx * 4);
        *reinterpret_cast<float4*>(out + (size_t)(ea + 1) * OUT_DIM + tx * 4) =
            make_float4(v0.y + C.x + D.x, v1.y + C.y + D.y,
                        v2.y + C.z + D.z, v3.y + C.w + D.w);
    }
}

extern "C" void kernel_launch(void* const* d_in, const int* in_sizes, int n_in,
                              void* d_out, int out_size)
{
    const float* h   = (const float*)d_in[0];       // [50000,128]
    const float* e   = (const float*)d_in[1];       // [800000,64]
    const int*   ei  = (const int*)d_in[2];         // [2,800000] int32 (or int64, detected)
    const float* We  = (const float*)d_in[3];       // [128,64]
    const float* Whu = (const float*)d_in[4];       // [128,128]
    const float* Whw = (const float*)d_in[5];       // [128,128]
    float*       out = (float*)d_out;               // [800000,128]

    detect_idx_kernel<<<1, 32>>>(ei);
    dim3 ngrid((N_NODES + 127) / 128, 2);
    node_proj_kernel<<<ngrid, 256>>>(h, Whu, Whw);
    edge_kernel<<<N_EDGES / 128, 256>>>(e, ei, We, out);
}